// round 3
// baseline (speedup 1.0000x reference)
#include <cuda_runtime.h>
#include <cuda_bf16.h>

#define N_NODES 100000
#define N_EDGES 1600000
#define DIM 128

// agg[i] = sum_{e: dst[e]==i} vals[e] * x[src[e]]   (51.2 MB scratch)
__device__ float g_agg[(size_t)N_NODES * DIM];

// ---------------------------------------------------------------------------
// Zero the aggregation scratch (atomics need initialized memory).
// ---------------------------------------------------------------------------
__global__ void zero_kernel() {
    int i = blockIdx.x * blockDim.x + threadIdx.x;
    int n4 = (N_NODES * DIM) / 4;
    if (i < n4)
        reinterpret_cast<float4*>(g_agg)[i] = make_float4(0.f, 0.f, 0.f, 0.f);
}

// ---------------------------------------------------------------------------
// Edge scatter: 4 edges per warp, lane l covers floats [4l, 4l+4).
// All 4 gathers issued before the 4 reductions -> MLP=4 per lane.
// red.global.add.v4.f32: no return trip, 16B per atomic op.
// ---------------------------------------------------------------------------
__global__ __launch_bounds__(256) void edge_kernel(const float* __restrict__ x,
                                                   const float* __restrict__ vals,
                                                   const int* __restrict__ src,
                                                   const int* __restrict__ dst) {
    const long w    = (long)blockIdx.x * 8 + (threadIdx.x >> 5);
    const int  lane = threadIdx.x & 31;
    const long e0   = w * 4;
    if (e0 >= N_EDGES) return;   // N_EDGES % 4 == 0, no tail

    int s[4], d[4];
    float v[4];
#pragma unroll
    for (int k = 0; k < 4; k++) {
        s[k] = __ldg(src + e0 + k);
        d[k] = __ldg(dst + e0 + k);
        v[k] = __ldg(vals + e0 + k);
    }

    float4 hv[4];
#pragma unroll
    for (int k = 0; k < 4; k++)
        hv[k] = *reinterpret_cast<const float4*>(x + (long)s[k] * DIM + lane * 4);

#pragma unroll
    for (int k = 0; k < 4; k++) {
        float* op = g_agg + (long)d[k] * DIM + lane * 4;
        asm volatile("red.global.add.v4.f32 [%0], {%1, %2, %3, %4};"
                     :: "l"(op),
                        "f"(hv[k].x * v[k]), "f"(hv[k].y * v[k]),
                        "f"(hv[k].z * v[k]), "f"(hv[k].w * v[k])
                     : "memory");
    }
}

// ---------------------------------------------------------------------------
// GEMM: out[n][o] = sum_k agg[n][k] * W[o][k], packed fma.rn.f32x2.
// W staged in padded shared (conflict-free .128 reads). Accumulator holds
// (even-k, odd-k) partials in a b64; both operand halves come straight from
// .128 loads. Fully overwrites out (no pre-zero needed).
// ---------------------------------------------------------------------------
__device__ __forceinline__ void fma2(unsigned long long& acc,
                                     unsigned long long a,
                                     unsigned long long b) {
    asm("fma.rn.f32x2 %0, %1, %2, %0;" : "+l"(acc) : "l"(a), "l"(b));
}

__global__ __launch_bounds__(256) void gemm_kernel(const float* __restrict__ W,
                                                   float* __restrict__ out) {
    extern __shared__ float w_s[]; // [128][132] padded
    const int tid = threadIdx.x;

    for (int idx = tid; idx < 128 * 32; idx += 256) {
        int row = idx >> 5;
        int c4  = idx & 31;
        float4 v = *reinterpret_cast<const float4*>(W + row * 128 + c4 * 4);
        *reinterpret_cast<float4*>(w_s + row * 132 + c4 * 4) = v;
    }
    __syncthreads();

    const int cid = tid & 31;
    const int rid = tid >> 5;
    const long row0 = (long)blockIdx.x * 64 + (long)rid * 8;

    const float* xp[8];
#pragma unroll
    for (int r = 0; r < 8; r++) {
        long row = row0 + r;
        if (row > N_NODES - 1) row = N_NODES - 1;  // clamp loads; writes guarded
        xp[r] = g_agg + row * DIM;
    }

    unsigned long long acc2[8][4];
#pragma unroll
    for (int r = 0; r < 8; r++)
#pragma unroll
        for (int j = 0; j < 4; j++) acc2[r][j] = 0ull;

#pragma unroll 4
    for (int k4 = 0; k4 < 32; ++k4) {
        ulonglong2 wp[4];
#pragma unroll
        for (int j = 0; j < 4; j++)
            wp[j] = *reinterpret_cast<const ulonglong2*>(w_s + (cid + 32 * j) * 132 + k4 * 4);
#pragma unroll
        for (int r = 0; r < 8; r++) {
            ulonglong2 xv = *reinterpret_cast<const ulonglong2*>(xp[r] + k4 * 4);
#pragma unroll
            for (int j = 0; j < 4; j++) {
                fma2(acc2[r][j], xv.x, wp[j].x);
                fma2(acc2[r][j], xv.y, wp[j].y);
            }
        }
    }

#pragma unroll
    for (int r = 0; r < 8; r++) {
        long row = row0 + r;
        if (row < N_NODES) {
            float* op = out + row * DIM;
#pragma unroll
            for (int j = 0; j < 4; j++) {
                unsigned long long u = acc2[r][j];
                float lo = __uint_as_float((unsigned)(u & 0xffffffffu));
                float hi = __uint_as_float((unsigned)(u >> 32));
                op[cid + 32 * j] = lo + hi;
            }
        }
    }
}

// ---------------------------------------------------------------------------
// Launch. Inputs: x, W, vals, src, dst. Output float32 [N_NODES, DIM].
// ---------------------------------------------------------------------------
extern "C" void kernel_launch(void* const* d_in, const int* in_sizes, int n_in,
                              void* d_out, int out_size) {
    const float* x    = (const float*)d_in[0];
    const float* W    = (const float*)d_in[1];
    const float* vals = (const float*)d_in[2];
    const int*   src  = (const int*)d_in[3];
    const int*   dst  = (const int*)d_in[4];
    float*       out  = (float*)d_out;

    const int smem = 128 * 132 * sizeof(float);
    cudaFuncSetAttribute(gemm_kernel, cudaFuncAttributeMaxDynamicSharedMemorySize, smem);

    // 1) zero aggregation scratch
    int n4 = (N_NODES * DIM) / 4;
    zero_kernel<<<(n4 + 255) / 256, 256>>>();

    // 2) agg[dst] += vals * x[src]   (4 edges per warp)
    long warps = N_EDGES / 4;                 // 400,000
    int blocks = (int)((warps + 7) / 8);      // 8 warps per block
    edge_kernel<<<blocks, 256>>>(x, vals, src, dst);

    // 3) out = agg @ W^T
    gemm_kernel<<<(N_NODES + 63) / 64, 256, smem>>>(W, out);
}

// round 4
// speedup vs baseline: 1.7577x; 1.7577x over previous
#include <cuda_runtime.h>
#include <cuda_bf16.h>

#define N_NODES 100000
#define N_EDGES 1600000
#define DIM 128
#define NB_SCAN ((N_NODES + 1023) / 1024)   // 98 scan blocks

// ---------------- device scratch (no allocs allowed) ----------------
__device__ float g_agg[(size_t)N_NODES * DIM]; // segment-summed messages (51.2 MB)
__device__ int   g_cnt[N_NODES];               // histogram -> cursor -> segment end
__device__ int   g_off[N_NODES];               // CSR start offsets
__device__ int   g_bsum[NB_SCAN];              // per-block scan sums
__device__ int2  g_edge[N_EDGES];              // dst-sorted (src, val-bits), 12.8 MB

// ---------------------------------------------------------------------------
__global__ void zero_cnt_kernel() {
    int i = blockIdx.x * blockDim.x + threadIdx.x;
    if (i < N_NODES) g_cnt[i] = 0;
}

__global__ void hist_kernel(const int* __restrict__ dst) {
    int e = blockIdx.x * blockDim.x + threadIdx.x;
    if (e < N_EDGES) atomicAdd(&g_cnt[__ldg(dst + e)], 1);
}

// Pass A: per-block (1024 elems) exclusive scan, block totals to g_bsum.
__global__ __launch_bounds__(256) void scan_a_kernel() {
    __shared__ int sh[256];
    const int b = blockIdx.x, t = threadIdx.x;
    const int base = b * 1024 + t * 4;

    int v[4], tsum = 0;
#pragma unroll
    for (int k = 0; k < 4; k++) {
        int idx = base + k;
        v[k] = (idx < N_NODES) ? g_cnt[idx] : 0;
        tsum += v[k];
    }
    sh[t] = tsum;
    __syncthreads();
    for (int off = 1; off < 256; off <<= 1) {
        int xv = (t >= off) ? sh[t - off] : 0;
        __syncthreads();
        sh[t] += xv;
        __syncthreads();
    }
    int run = sh[t] - tsum;  // exclusive
    if (t == 255) g_bsum[b] = sh[255];
#pragma unroll
    for (int k = 0; k < 4; k++) {
        int idx = base + k;
        if (idx < N_NODES) g_off[idx] = run;
        run += v[k];
    }
}

// Pass B: add block-sum prefix; initialize scatter cursor (g_cnt = off).
__global__ __launch_bounds__(256) void scan_b_kernel() {
    __shared__ int sh[256];
    const int b = blockIdx.x, t = threadIdx.x;
    sh[t] = (t < b) ? g_bsum[t] : 0;
    __syncthreads();
    for (int off = 128; off > 0; off >>= 1) {
        if (t < off) sh[t] += sh[t + off];
        __syncthreads();
    }
    const int pre = sh[0];
    const int base = b * 1024 + t * 4;
#pragma unroll
    for (int k = 0; k < 4; k++) {
        int idx = base + k;
        if (idx < N_NODES) {
            int o = g_off[idx] + pre;
            g_off[idx] = o;
            g_cnt[idx] = o;  // cursor; after scatter == segment end
        }
    }
}

__global__ void scatter_kernel(const float* __restrict__ vals,
                               const int* __restrict__ src,
                               const int* __restrict__ dst) {
    int e = blockIdx.x * blockDim.x + threadIdx.x;
    if (e >= N_EDGES) return;
    int d = __ldg(dst + e);
    int pos = atomicAdd(&g_cnt[d], 1);
    int2 p;
    p.x = __ldg(src + e);
    p.y = __float_as_int(__ldg(vals + e));
    g_edge[pos] = p;  // single 8B store
}

// ---------------------------------------------------------------------------
// Per-node reduce: warp per node, lane l covers floats [4l, 4l+4).
// 4 independent gathers in flight per lane (MLP=4). No fp atomics.
// agg row fully written, including zero rows.
// ---------------------------------------------------------------------------
__global__ __launch_bounds__(256) void reduce_kernel(const float* __restrict__ x) {
    const int n    = blockIdx.x * 8 + (threadIdx.x >> 5);
    const int lane = threadIdx.x & 31;
    if (n >= N_NODES) return;

    int e   = g_off[n];
    int end = g_cnt[n];

    float4 acc = make_float4(0.f, 0.f, 0.f, 0.f);

    for (; e + 3 < end; e += 4) {
        int2 p0 = __ldg(g_edge + e);
        int2 p1 = __ldg(g_edge + e + 1);
        int2 p2 = __ldg(g_edge + e + 2);
        int2 p3 = __ldg(g_edge + e + 3);
        float4 h0 = *reinterpret_cast<const float4*>(x + (long)p0.x * DIM + lane * 4);
        float4 h1 = *reinterpret_cast<const float4*>(x + (long)p1.x * DIM + lane * 4);
        float4 h2 = *reinterpret_cast<const float4*>(x + (long)p2.x * DIM + lane * 4);
        float4 h3 = *reinterpret_cast<const float4*>(x + (long)p3.x * DIM + lane * 4);
        float v0 = __int_as_float(p0.y), v1 = __int_as_float(p1.y);
        float v2 = __int_as_float(p2.y), v3 = __int_as_float(p3.y);
        acc.x += v0 * h0.x + v1 * h1.x + v2 * h2.x + v3 * h3.x;
        acc.y += v0 * h0.y + v1 * h1.y + v2 * h2.y + v3 * h3.y;
        acc.z += v0 * h0.z + v1 * h1.z + v2 * h2.z + v3 * h3.z;
        acc.w += v0 * h0.w + v1 * h1.w + v2 * h2.w + v3 * h3.w;
    }
    for (; e < end; e++) {
        int2 p0 = __ldg(g_edge + e);
        float4 h0 = *reinterpret_cast<const float4*>(x + (long)p0.x * DIM + lane * 4);
        float v0 = __int_as_float(p0.y);
        acc.x += v0 * h0.x;
        acc.y += v0 * h0.y;
        acc.z += v0 * h0.z;
        acc.w += v0 * h0.w;
    }
    *reinterpret_cast<float4*>(g_agg + (long)n * DIM + lane * 4) = acc;
}

// ---------------------------------------------------------------------------
// GEMM (plain FFMA, R1 design): out[n][o] = sum_k agg[n][k] * W[o][k].
// W staged fully in shared (128 x 132 padded). 8 rows/warp, 4 cols/lane.
// ---------------------------------------------------------------------------
__global__ __launch_bounds__(256) void gemm_kernel(const float* __restrict__ W,
                                                   float* __restrict__ out) {
    extern __shared__ float w_s[]; // [128][132]
    const int tid = threadIdx.x;

    for (int idx = tid; idx < 128 * 32; idx += 256) {
        int row = idx >> 5;
        int c4  = idx & 31;
        float4 v = *reinterpret_cast<const float4*>(W + row * 128 + c4 * 4);
        *reinterpret_cast<float4*>(w_s + row * 132 + c4 * 4) = v;
    }
    __syncthreads();

    const int cid = tid & 31;
    const int rid = tid >> 5;
    const long row0 = (long)blockIdx.x * 64 + (long)rid * 8;

    const float* xp[8];
#pragma unroll
    for (int r = 0; r < 8; r++) {
        long row = row0 + r;
        if (row > N_NODES - 1) row = N_NODES - 1;  // clamp loads; writes guarded
        xp[r] = g_agg + row * DIM;
    }

    float acc[8][4];
#pragma unroll
    for (int r = 0; r < 8; r++)
#pragma unroll
        for (int j = 0; j < 4; j++) acc[r][j] = 0.f;

#pragma unroll 4
    for (int k4 = 0; k4 < 32; ++k4) {
        float4 wv[4];
#pragma unroll
        for (int j = 0; j < 4; j++)
            wv[j] = *reinterpret_cast<const float4*>(w_s + (cid + 32 * j) * 132 + k4 * 4);
#pragma unroll
        for (int r = 0; r < 8; r++) {
            float4 xv = *reinterpret_cast<const float4*>(xp[r] + k4 * 4);
#pragma unroll
            for (int j = 0; j < 4; j++) {
                acc[r][j] += xv.x * wv[j].x;
                acc[r][j] += xv.y * wv[j].y;
                acc[r][j] += xv.z * wv[j].z;
                acc[r][j] += xv.w * wv[j].w;
            }
        }
    }

#pragma unroll
    for (int r = 0; r < 8; r++) {
        long row = row0 + r;
        if (row < N_NODES) {
            float* op = out + row * DIM;
#pragma unroll
            for (int j = 0; j < 4; j++) op[cid + 32 * j] = acc[r][j];
        }
    }
}

// ---------------------------------------------------------------------------
// Launch. Inputs: x, W, vals, src, dst. Output float32 [N_NODES, DIM].
// out = segment_sum(vals * x[src], dst) @ W^T   (linearity reassociation)
// ---------------------------------------------------------------------------
extern "C" void kernel_launch(void* const* d_in, const int* in_sizes, int n_in,
                              void* d_out, int out_size) {
    const float* x    = (const float*)d_in[0];
    const float* W    = (const float*)d_in[1];
    const float* vals = (const float*)d_in[2];
    const int*   src  = (const int*)d_in[3];
    const int*   dst  = (const int*)d_in[4];
    float*       out  = (float*)d_out;

    const int smem = 128 * 132 * sizeof(float);
    cudaFuncSetAttribute(gemm_kernel, cudaFuncAttributeMaxDynamicSharedMemorySize, smem);

    const int EB = (N_EDGES + 255) / 256;

    zero_cnt_kernel<<<(N_NODES + 255) / 256, 256>>>();
    hist_kernel<<<EB, 256>>>(dst);
    scan_a_kernel<<<NB_SCAN, 256>>>();
    scan_b_kernel<<<NB_SCAN, 256>>>();
    scatter_kernel<<<EB, 256>>>(vals, src, dst);
    reduce_kernel<<<(N_NODES + 7) / 8, 256>>>(x);
    gemm_kernel<<<(N_NODES + 63) / 64, 256, smem>>>(W, out);
}

// round 5
// speedup vs baseline: 1.8561x; 1.0560x over previous
#include <cuda_runtime.h>
#include <cuda_bf16.h>

#define N_NODES 100000
#define N_EDGES 1600000
#define DIM 128
#define NB_SCAN ((N_NODES + 1023) / 1024)   // 98 scan blocks

// ---------------- device scratch (no allocs allowed) ----------------
__device__ int  g_cnt[N_NODES];   // histogram -> cursor -> segment end
__device__ int  g_off[N_NODES];   // CSR start offsets
__device__ int  g_bsum[NB_SCAN];  // per-block scan sums
__device__ int2 g_edge[N_EDGES];  // dst-sorted (src, val-bits), 12.8 MB

// ---------------------------------------------------------------------------
__global__ void zero_cnt_kernel() {
    int i = blockIdx.x * blockDim.x + threadIdx.x;
    if (i < N_NODES) g_cnt[i] = 0;
}

__global__ void hist_kernel(const int* __restrict__ dst) {
    int e = blockIdx.x * blockDim.x + threadIdx.x;
    if (e < N_EDGES) atomicAdd(&g_cnt[__ldg(dst + e)], 1);
}

// Pass A: per-block (1024 elems) exclusive scan, block totals to g_bsum.
__global__ __launch_bounds__(256) void scan_a_kernel() {
    __shared__ int sh[256];
    const int b = blockIdx.x, t = threadIdx.x;
    const int base = b * 1024 + t * 4;

    int v[4], tsum = 0;
#pragma unroll
    for (int k = 0; k < 4; k++) {
        int idx = base + k;
        v[k] = (idx < N_NODES) ? g_cnt[idx] : 0;
        tsum += v[k];
    }
    sh[t] = tsum;
    __syncthreads();
    for (int off = 1; off < 256; off <<= 1) {
        int xv = (t >= off) ? sh[t - off] : 0;
        __syncthreads();
        sh[t] += xv;
        __syncthreads();
    }
    int run = sh[t] - tsum;  // exclusive
    if (t == 255) g_bsum[b] = sh[255];
#pragma unroll
    for (int k = 0; k < 4; k++) {
        int idx = base + k;
        if (idx < N_NODES) g_off[idx] = run;
        run += v[k];
    }
}

// Pass B: add block-sum prefix; initialize scatter cursor (g_cnt = off).
__global__ __launch_bounds__(256) void scan_b_kernel() {
    __shared__ int sh[256];
    const int b = blockIdx.x, t = threadIdx.x;
    sh[t] = (t < b) ? g_bsum[t] : 0;
    __syncthreads();
    for (int off = 128; off > 0; off >>= 1) {
        if (t < off) sh[t] += sh[t + off];
        __syncthreads();
    }
    const int pre = sh[0];
    const int base = b * 1024 + t * 4;
#pragma unroll
    for (int k = 0; k < 4; k++) {
        int idx = base + k;
        if (idx < N_NODES) {
            int o = g_off[idx] + pre;
            g_off[idx] = o;
            g_cnt[idx] = o;  // cursor; after scatter == segment end
        }
    }
}

__global__ void scatter_kernel(const float* __restrict__ vals,
                               const int* __restrict__ src,
                               const int* __restrict__ dst) {
    int e = blockIdx.x * blockDim.x + threadIdx.x;
    if (e >= N_EDGES) return;
    int d = __ldg(dst + e);
    int pos = atomicAdd(&g_cnt[d], 1);
    int2 p;
    p.x = __ldg(src + e);
    p.y = __float_as_int(__ldg(vals + e));
    g_edge[pos] = p;  // single 8B store
}

// ---------------------------------------------------------------------------
// Fused gather + GEMM.
// Block = 256 threads (8 warps), 64 nodes per block.
// Phase 0: all threads stage W into w_s[128][132].
// Phase 1: warp w gathers its 8 node-rows (MLP=4 per lane) and stores each
//          row into agg_s[64][132] (conflict-free .128 stores).
// Phase 2 (after __syncthreads): R1-style GEMM — warp w computes 8 rows,
//          lane c cols {c, c+32, c+64, c+96}; agg rows come from shared as
//          broadcast .128 loads; writes out directly (coalesced).
// Gather stalls of some warps overlap with FFMA issue of others.
// ---------------------------------------------------------------------------
#define SMEM_FUSED ((128 * 132 + 64 * 132) * 4)

__global__ __launch_bounds__(256) void fused_kernel(const float* __restrict__ x,
                                                    const float* __restrict__ W,
                                                    float* __restrict__ out) {
    extern __shared__ float smem[];
    float* w_s   = smem;               // [128][132]
    float* agg_s = smem + 128 * 132;   // [64][132]

    const int tid  = threadIdx.x;
    const int lane = tid & 31;
    const int rid  = tid >> 5;         // warp id 0..7
    const long node0 = (long)blockIdx.x * 64;

    // Phase 0: stage W (4096 float4, 16 per thread)
    for (int idx = tid; idx < 128 * 32; idx += 256) {
        int row = idx >> 5;
        int c4  = idx & 31;
        float4 v = *reinterpret_cast<const float4*>(W + row * 128 + c4 * 4);
        *reinterpret_cast<float4*>(w_s + row * 132 + c4 * 4) = v;
    }

    // Phase 1: gather 8 nodes per warp into agg_s
#pragma unroll 1
    for (int r = 0; r < 8; r++) {
        const int  lr = rid * 8 + r;        // local row 0..63
        const long n  = node0 + lr;

        float4 acc = make_float4(0.f, 0.f, 0.f, 0.f);
        if (n < N_NODES) {
            int e   = __ldg(g_off + n);
            int end = __ldg(g_cnt + n);
            for (; e + 3 < end; e += 4) {
                int2 p0 = __ldg(g_edge + e);
                int2 p1 = __ldg(g_edge + e + 1);
                int2 p2 = __ldg(g_edge + e + 2);
                int2 p3 = __ldg(g_edge + e + 3);
                float4 h0 = *reinterpret_cast<const float4*>(x + (long)p0.x * DIM + lane * 4);
                float4 h1 = *reinterpret_cast<const float4*>(x + (long)p1.x * DIM + lane * 4);
                float4 h2 = *reinterpret_cast<const float4*>(x + (long)p2.x * DIM + lane * 4);
                float4 h3 = *reinterpret_cast<const float4*>(x + (long)p3.x * DIM + lane * 4);
                float v0 = __int_as_float(p0.y), v1 = __int_as_float(p1.y);
                float v2 = __int_as_float(p2.y), v3 = __int_as_float(p3.y);
                acc.x += v0 * h0.x + v1 * h1.x + v2 * h2.x + v3 * h3.x;
                acc.y += v0 * h0.y + v1 * h1.y + v2 * h2.y + v3 * h3.y;
                acc.z += v0 * h0.z + v1 * h1.z + v2 * h2.z + v3 * h3.z;
                acc.w += v0 * h0.w + v1 * h1.w + v2 * h2.w + v3 * h3.w;
            }
            for (; e < end; e++) {
                int2 p0 = __ldg(g_edge + e);
                float4 h0 = *reinterpret_cast<const float4*>(x + (long)p0.x * DIM + lane * 4);
                float v0 = __int_as_float(p0.y);
                acc.x += v0 * h0.x;
                acc.y += v0 * h0.y;
                acc.z += v0 * h0.z;
                acc.w += v0 * h0.w;
            }
        }
        *reinterpret_cast<float4*>(agg_s + lr * 132 + lane * 4) = acc;
    }

    __syncthreads();

    // Phase 2: GEMM on shared agg rows
    const int cid = lane;
    float acc[8][4];
#pragma unroll
    for (int r = 0; r < 8; r++)
#pragma unroll
        for (int j = 0; j < 4; j++) acc[r][j] = 0.f;

    const float* agg_base = agg_s + rid * 8 * 132;

#pragma unroll 4
    for (int k4 = 0; k4 < 32; ++k4) {
        float4 wv[4];
#pragma unroll
        for (int j = 0; j < 4; j++)
            wv[j] = *reinterpret_cast<const float4*>(w_s + (cid + 32 * j) * 132 + k4 * 4);
#pragma unroll
        for (int r = 0; r < 8; r++) {
            float4 xv = *reinterpret_cast<const float4*>(agg_base + r * 132 + k4 * 4);
#pragma unroll
            for (int j = 0; j < 4; j++) {
                acc[r][j] += xv.x * wv[j].x;
                acc[r][j] += xv.y * wv[j].y;
                acc[r][j] += xv.z * wv[j].z;
                acc[r][j] += xv.w * wv[j].w;
            }
        }
    }

#pragma unroll
    for (int r = 0; r < 8; r++) {
        long row = node0 + rid * 8 + r;
        if (row < N_NODES) {
            float* op = out + row * DIM;
#pragma unroll
            for (int j = 0; j < 4; j++) op[cid + 32 * j] = acc[r][j];
        }
    }
}

// ---------------------------------------------------------------------------
// Launch. Inputs: x, W, vals, src, dst. Output float32 [N_NODES, DIM].
// out = segment_sum(vals * x[src], dst) @ W^T   (linearity reassociation)
// ---------------------------------------------------------------------------
extern "C" void kernel_launch(void* const* d_in, const int* in_sizes, int n_in,
                              void* d_out, int out_size) {
    const float* x    = (const float*)d_in[0];
    const float* W    = (const float*)d_in[1];
    const float* vals = (const float*)d_in[2];
    const int*   src  = (const int*)d_in[3];
    const int*   dst  = (const int*)d_in[4];
    float*       out  = (float*)d_out;

    cudaFuncSetAttribute(fused_kernel, cudaFuncAttributeMaxDynamicSharedMemorySize,
                         SMEM_FUSED);

    const int EB = (N_EDGES + 255) / 256;

    zero_cnt_kernel<<<(N_NODES + 255) / 256, 256>>>();
    hist_kernel<<<EB, 256>>>(dst);
    scan_a_kernel<<<NB_SCAN, 256>>>();
    scan_b_kernel<<<NB_SCAN, 256>>>();
    scatter_kernel<<<EB, 256>>>(vals, src, dst);
    fused_kernel<<<(N_NODES + 63) / 64, 256, SMEM_FUSED>>>(x, W, out);
}

// round 6
// speedup vs baseline: 1.8735x; 1.0094x over previous
#include <cuda_runtime.h>
#include <cuda_bf16.h>

#define N_NODES 100000
#define N_EDGES 1600000
#define DIM 128
#define NB_SCAN ((N_NODES + 1023) / 1024)   // 98 scan blocks

// ---------------- device scratch (no allocs allowed) ----------------
__device__ int  g_cnt[N_NODES];   // histogram -> cursor -> segment end
__device__ int  g_off[N_NODES];   // CSR start offsets
__device__ int  g_bsum[NB_SCAN];  // per-block scan sums
__device__ int2 g_edge[N_EDGES];  // dst-sorted (src, val-bits), 12.8 MB

// ---------------------------------------------------------------------------
__global__ void zero_cnt_kernel() {
    int i = blockIdx.x * blockDim.x + threadIdx.x;
    if (i < N_NODES) g_cnt[i] = 0;
}

__global__ void hist_kernel(const int* __restrict__ dst) {
    int e = blockIdx.x * blockDim.x + threadIdx.x;
    if (e < N_EDGES) atomicAdd(&g_cnt[__ldg(dst + e)], 1);
}

// Pass A: per-block (1024 elems) exclusive scan, block totals to g_bsum.
__global__ __launch_bounds__(256) void scan_a_kernel() {
    __shared__ int sh[256];
    const int b = blockIdx.x, t = threadIdx.x;
    const int base = b * 1024 + t * 4;

    int v[4], tsum = 0;
#pragma unroll
    for (int k = 0; k < 4; k++) {
        int idx = base + k;
        v[k] = (idx < N_NODES) ? g_cnt[idx] : 0;
        tsum += v[k];
    }
    sh[t] = tsum;
    __syncthreads();
    for (int off = 1; off < 256; off <<= 1) {
        int xv = (t >= off) ? sh[t - off] : 0;
        __syncthreads();
        sh[t] += xv;
        __syncthreads();
    }
    int run = sh[t] - tsum;  // exclusive
    if (t == 255) g_bsum[b] = sh[255];
#pragma unroll
    for (int k = 0; k < 4; k++) {
        int idx = base + k;
        if (idx < N_NODES) g_off[idx] = run;
        run += v[k];
    }
}

// Pass B: add block-sum prefix; initialize scatter cursor (g_cnt = off).
__global__ __launch_bounds__(256) void scan_b_kernel() {
    __shared__ int sh[256];
    const int b = blockIdx.x, t = threadIdx.x;
    sh[t] = (t < b) ? g_bsum[t] : 0;
    __syncthreads();
    for (int off = 128; off > 0; off >>= 1) {
        if (t < off) sh[t] += sh[t + off];
        __syncthreads();
    }
    const int pre = sh[0];
    const int base = b * 1024 + t * 4;
#pragma unroll
    for (int k = 0; k < 4; k++) {
        int idx = base + k;
        if (idx < N_NODES) {
            int o = g_off[idx] + pre;
            g_off[idx] = o;
            g_cnt[idx] = o;  // cursor; after scatter == segment end
        }
    }
}

__global__ void scatter_kernel(const float* __restrict__ vals,
                               const int* __restrict__ src,
                               const int* __restrict__ dst) {
    int e = blockIdx.x * blockDim.x + threadIdx.x;
    if (e >= N_EDGES) return;
    int d = __ldg(dst + e);
    int pos = atomicAdd(&g_cnt[d], 1);
    int2 p;
    p.x = __ldg(src + e);
    p.y = __float_as_int(__ldg(vals + e));
    g_edge[pos] = p;  // single 8B store
}

// ---------------------------------------------------------------------------
// Fused gather + GEMM, warp-independent pipeline.
// Block = 256 threads (8 warps), 64 nodes per block; warp w owns nodes
// [w*8, w*8+8) of the tile. Its agg rows in shared are PRIVATE to the warp,
// so no block barrier is needed between gather and GEMM — only __syncwarp().
// Warps skew freely: one warp's L2 gather stalls overlap another's FFMAs.
// ---------------------------------------------------------------------------
#define SMEM_FUSED ((128 * 132 + 64 * 132) * 4)

__global__ __launch_bounds__(256) void fused_kernel(const float* __restrict__ x,
                                                    const float* __restrict__ W,
                                                    float* __restrict__ out) {
    extern __shared__ float smem[];
    float* w_s   = smem;               // [128][132]
    float* agg_s = smem + 128 * 132;   // [64][132], rows rid*8.. private per warp

    const int tid  = threadIdx.x;
    const int lane = tid & 31;
    const int rid  = tid >> 5;         // warp id 0..7
    const long node0 = (long)blockIdx.x * 64;

    // Phase 0: stage W (4096 float4, 16 per thread). Only block-wide sync.
    for (int idx = tid; idx < 128 * 32; idx += 256) {
        int row = idx >> 5;
        int c4  = idx & 31;
        float4 v = *reinterpret_cast<const float4*>(W + row * 128 + c4 * 4);
        *reinterpret_cast<float4*>(w_s + row * 132 + c4 * 4) = v;
    }
    __syncthreads();

    // Phase 1: gather this warp's 8 node rows into its private agg rows.
#pragma unroll 1
    for (int r = 0; r < 8; r++) {
        const int  lr = rid * 8 + r;        // local row 0..63
        const long n  = node0 + lr;

        float4 acc = make_float4(0.f, 0.f, 0.f, 0.f);
        if (n < N_NODES) {
            int e   = __ldg(g_off + n);
            int end = __ldg(g_cnt + n);
            for (; e + 3 < end; e += 4) {
                int2 p0 = __ldg(g_edge + e);
                int2 p1 = __ldg(g_edge + e + 1);
                int2 p2 = __ldg(g_edge + e + 2);
                int2 p3 = __ldg(g_edge + e + 3);
                float4 h0 = *reinterpret_cast<const float4*>(x + (long)p0.x * DIM + lane * 4);
                float4 h1 = *reinterpret_cast<const float4*>(x + (long)p1.x * DIM + lane * 4);
                float4 h2 = *reinterpret_cast<const float4*>(x + (long)p2.x * DIM + lane * 4);
                float4 h3 = *reinterpret_cast<const float4*>(x + (long)p3.x * DIM + lane * 4);
                float v0 = __int_as_float(p0.y), v1 = __int_as_float(p1.y);
                float v2 = __int_as_float(p2.y), v3 = __int_as_float(p3.y);
                acc.x += v0 * h0.x + v1 * h1.x + v2 * h2.x + v3 * h3.x;
                acc.y += v0 * h0.y + v1 * h1.y + v2 * h2.y + v3 * h3.y;
                acc.z += v0 * h0.z + v1 * h1.z + v2 * h2.z + v3 * h3.z;
                acc.w += v0 * h0.w + v1 * h1.w + v2 * h2.w + v3 * h3.w;
            }
            for (; e < end; e++) {
                int2 p0 = __ldg(g_edge + e);
                float4 h0 = *reinterpret_cast<const float4*>(x + (long)p0.x * DIM + lane * 4);
                float v0 = __int_as_float(p0.y);
                acc.x += v0 * h0.x;
                acc.y += v0 * h0.y;
                acc.z += v0 * h0.z;
                acc.w += v0 * h0.w;
            }
        }
        *reinterpret_cast<float4*>(agg_s + lr * 132 + lane * 4) = acc;
    }

    __syncwarp();  // cross-lane visibility of this warp's own agg rows

    // Phase 2: GEMM on this warp's private shared agg rows.
    const int cid = lane;
    float acc[8][4];
#pragma unroll
    for (int r = 0; r < 8; r++)
#pragma unroll
        for (int j = 0; j < 4; j++) acc[r][j] = 0.f;

    const float* agg_base = agg_s + rid * 8 * 132;

#pragma unroll 4
    for (int k4 = 0; k4 < 32; ++k4) {
        float4 wv[4];
#pragma unroll
        for (int j = 0; j < 4; j++)
            wv[j] = *reinterpret_cast<const float4*>(w_s + (cid + 32 * j) * 132 + k4 * 4);
#pragma unroll
        for (int r = 0; r < 8; r++) {
            float4 xv = *reinterpret_cast<const float4*>(agg_base + r * 132 + k4 * 4);
#pragma unroll
            for (int j = 0; j < 4; j++) {
                acc[r][j] += xv.x * wv[j].x;
                acc[r][j] += xv.y * wv[j].y;
                acc[r][j] += xv.z * wv[j].z;
                acc[r][j] += xv.w * wv[j].w;
            }
        }
    }

#pragma unroll
    for (int r = 0; r < 8; r++) {
        long row = node0 + rid * 8 + r;
        if (row < N_NODES) {
            float* op = out + row * DIM;
#pragma unroll
            for (int j = 0; j < 4; j++) op[cid + 32 * j] = acc[r][j];
        }
    }
}

// ---------------------------------------------------------------------------
// Launch. Inputs: x, W, vals, src, dst. Output float32 [N_NODES, DIM].
// out = segment_sum(vals * x[src], dst) @ W^T   (linearity reassociation)
// ---------------------------------------------------------------------------
extern "C" void kernel_launch(void* const* d_in, const int* in_sizes, int n_in,
                              void* d_out, int out_size) {
    const float* x    = (const float*)d_in[0];
    const float* W    = (const float*)d_in[1];
    const float* vals = (const float*)d_in[2];
    const int*   src  = (const int*)d_in[3];
    const int*   dst  = (const int*)d_in[4];
    float*       out  = (float*)d_out;

    cudaFuncSetAttribute(fused_kernel, cudaFuncAttributeMaxDynamicSharedMemorySize,
                         SMEM_FUSED);

    const int EB = (N_EDGES + 255) / 256;

    zero_cnt_kernel<<<(N_NODES + 255) / 256, 256>>>();
    hist_kernel<<<EB, 256>>>(dst);
    scan_a_kernel<<<NB_SCAN, 256>>>();
    scan_b_kernel<<<NB_SCAN, 256>>>();
    scatter_kernel<<<EB, 256>>>(vals, src, dst);
    fused_kernel<<<(N_NODES + 63) / 64, 256, SMEM_FUSED>>>(x, W, out);
}

// round 8
// speedup vs baseline: 2.1500x; 1.1475x over previous
#include <cuda_runtime.h>
#include <cuda_bf16.h>
#include <cstdint>

#define N_NODES 100000
#define N_EDGES 1600000
#define DIM 128
#define NB_SCAN ((N_NODES + 1023) / 1024)   // 98 scan blocks

// ---------------- device scratch (no allocs allowed) ----------------
__device__ __align__(16) float g_agg[(size_t)N_NODES * DIM]; // 51.2 MB
__device__ int  g_cnt[N_NODES];   // histogram -> cursor -> segment end
__device__ int  g_off[N_NODES];   // CSR start offsets
__device__ int  g_bsum[NB_SCAN];  // per-block scan sums
__device__ int2 g_edge[N_EDGES];  // dst-sorted (src, val-bits), 12.8 MB

// ---------------------------------------------------------------------------
__global__ void zero_cnt_kernel() {
    int i = blockIdx.x * blockDim.x + threadIdx.x;
    if (i < N_NODES) g_cnt[i] = 0;
}

__global__ void hist_kernel(const int* __restrict__ dst) {
    int e = blockIdx.x * blockDim.x + threadIdx.x;
    if (e < N_EDGES) atomicAdd(&g_cnt[__ldg(dst + e)], 1);
}

__global__ __launch_bounds__(256) void scan_a_kernel() {
    __shared__ int sh[256];
    const int b = blockIdx.x, t = threadIdx.x;
    const int base = b * 1024 + t * 4;

    int v[4], tsum = 0;
#pragma unroll
    for (int k = 0; k < 4; k++) {
        int idx = base + k;
        v[k] = (idx < N_NODES) ? g_cnt[idx] : 0;
        tsum += v[k];
    }
    sh[t] = tsum;
    __syncthreads();
    for (int off = 1; off < 256; off <<= 1) {
        int xv = (t >= off) ? sh[t - off] : 0;
        __syncthreads();
        sh[t] += xv;
        __syncthreads();
    }
    int run = sh[t] - tsum;
    if (t == 255) g_bsum[b] = sh[255];
#pragma unroll
    for (int k = 0; k < 4; k++) {
        int idx = base + k;
        if (idx < N_NODES) g_off[idx] = run;
        run += v[k];
    }
}

__global__ __launch_bounds__(256) void scan_b_kernel() {
    __shared__ int sh[256];
    const int b = blockIdx.x, t = threadIdx.x;
    sh[t] = (t < b) ? g_bsum[t] : 0;
    __syncthreads();
    for (int off = 128; off > 0; off >>= 1) {
        if (t < off) sh[t] += sh[t + off];
        __syncthreads();
    }
    const int pre = sh[0];
    const int base = b * 1024 + t * 4;
#pragma unroll
    for (int k = 0; k < 4; k++) {
        int idx = base + k;
        if (idx < N_NODES) {
            int o = g_off[idx] + pre;
            g_off[idx] = o;
            g_cnt[idx] = o;
        }
    }
}

__global__ void scatter_kernel(const float* __restrict__ vals,
                               const int* __restrict__ src,
                               const int* __restrict__ dst) {
    int e = blockIdx.x * blockDim.x + threadIdx.x;
    if (e >= N_EDGES) return;
    int d = __ldg(dst + e);
    int pos = atomicAdd(&g_cnt[d], 1);
    int2 p;
    p.x = __ldg(src + e);
    p.y = __float_as_int(__ldg(vals + e));
    g_edge[pos] = p;
}

// ---------------------------------------------------------------------------
// Per-node reduce (R4, proven): warp per node, MLP=4 gathers in flight.
// ---------------------------------------------------------------------------
__global__ __launch_bounds__(256) void reduce_kernel(const float* __restrict__ x) {
    const int n    = blockIdx.x * 8 + (threadIdx.x >> 5);
    const int lane = threadIdx.x & 31;
    if (n >= N_NODES) return;

    int e   = g_off[n];
    int end = g_cnt[n];

    float4 acc = make_float4(0.f, 0.f, 0.f, 0.f);
    for (; e + 3 < end; e += 4) {
        int2 p0 = __ldg(g_edge + e);
        int2 p1 = __ldg(g_edge + e + 1);
        int2 p2 = __ldg(g_edge + e + 2);
        int2 p3 = __ldg(g_edge + e + 3);
        float4 h0 = *reinterpret_cast<const float4*>(x + (long)p0.x * DIM + lane * 4);
        float4 h1 = *reinterpret_cast<const float4*>(x + (long)p1.x * DIM + lane * 4);
        float4 h2 = *reinterpret_cast<const float4*>(x + (long)p2.x * DIM + lane * 4);
        float4 h3 = *reinterpret_cast<const float4*>(x + (long)p3.x * DIM + lane * 4);
        float v0 = __int_as_float(p0.y), v1 = __int_as_float(p1.y);
        float v2 = __int_as_float(p2.y), v3 = __int_as_float(p3.y);
        acc.x += v0 * h0.x + v1 * h1.x + v2 * h2.x + v3 * h3.x;
        acc.y += v0 * h0.y + v1 * h1.y + v2 * h2.y + v3 * h3.y;
        acc.z += v0 * h0.z + v1 * h1.z + v2 * h2.z + v3 * h3.z;
        acc.w += v0 * h0.w + v1 * h1.w + v2 * h2.w + v3 * h3.w;
    }
    for (; e < end; e++) {
        int2 p0 = __ldg(g_edge + e);
        float4 h0 = *reinterpret_cast<const float4*>(x + (long)p0.x * DIM + lane * 4);
        float v0 = __int_as_float(p0.y);
        acc.x += v0 * h0.x;
        acc.y += v0 * h0.y;
        acc.z += v0 * h0.z;
        acc.w += v0 * h0.w;
    }
    *reinterpret_cast<float4*>(g_agg + (long)n * DIM + lane * 4) = acc;
}

// ---------------------------------------------------------------------------
// TF32 tensor-core GEMM via mma.sync (sm_80 path, no 'a'-feature needed):
//   out[m][n] = sum_k agg[m][k] * W[n][k]
// 3xTF32 decomposition for fp32-grade accuracy:
//   a = big(a) + small(a);  D += Ab*Bb + Ab*Bs + As*Bb
// Block: 128 rows, 8 warps; warp w owns rows [w*16, w*16+16), all 128 cols.
// W staged in shared [128][132] (B-fragment LDS bank-conflict-free).
// ---------------------------------------------------------------------------
__device__ __forceinline__ uint32_t f2tf32(float f) {
    uint32_t r;
    asm("cvt.rna.tf32.f32 %0, %1;" : "=r"(r) : "f"(f));
    return r;
}

__device__ __forceinline__ void mma_tf32(float* d, const uint32_t* a,
                                         uint32_t b0, uint32_t b1) {
    asm("mma.sync.aligned.m16n8k8.row.col.f32.tf32.tf32.f32 "
        "{%0,%1,%2,%3}, {%4,%5,%6,%7}, {%8,%9}, {%0,%1,%2,%3};"
        : "+f"(d[0]), "+f"(d[1]), "+f"(d[2]), "+f"(d[3])
        : "r"(a[0]), "r"(a[1]), "r"(a[2]), "r"(a[3]), "r"(b0), "r"(b1));
}

__global__ __launch_bounds__(256) void mma_gemm_kernel(const float* __restrict__ W,
                                                       float* __restrict__ out) {
    extern __shared__ float w_s[];  // [128][132]
    const int tid  = threadIdx.x;
    const int lane = tid & 31;
    const int wid  = tid >> 5;
    const int g    = lane >> 2;    // group id (row within fragment)
    const int tg   = lane & 3;     // thread-in-group (col within fragment)

    // Stage W
    for (int idx = tid; idx < 128 * 32; idx += 256) {
        int row = idx >> 5;
        int c4  = idx & 31;
        float4 v = *reinterpret_cast<const float4*>(W + row * 128 + c4 * 4);
        *reinterpret_cast<float4*>(w_s + row * 132 + c4 * 4) = v;
    }
    __syncthreads();

    const long row0 = (long)blockIdx.x * 128 + wid * 16;
    const long rA0  = row0 + g;        // A-fragment row (a0, a2)
    const long rA1  = row0 + g + 8;    // A-fragment row (a1, a3)
    const bool ok0  = rA0 < N_NODES;
    const bool ok1  = rA1 < N_NODES;
    const float* aggp0 = g_agg + (ok0 ? rA0 : 0) * DIM;
    const float* aggp1 = g_agg + (ok1 ? rA1 : 0) * DIM;

    float acc[16][4];
#pragma unroll
    for (int nt = 0; nt < 16; nt++)
#pragma unroll
        for (int j = 0; j < 4; j++) acc[nt][j] = 0.f;

#pragma unroll 1
    for (int ks = 0; ks < 16; ks++) {
        // A fragment (f32), zero for out-of-range rows
        float af[4];
        af[0] = ok0 ? __ldg(aggp0 + ks * 8 + tg)     : 0.f;
        af[1] = ok1 ? __ldg(aggp1 + ks * 8 + tg)     : 0.f;
        af[2] = ok0 ? __ldg(aggp0 + ks * 8 + tg + 4) : 0.f;
        af[3] = ok1 ? __ldg(aggp1 + ks * 8 + tg + 4) : 0.f;

        uint32_t ab[4], as[4];
#pragma unroll
        for (int i = 0; i < 4; i++) {
            ab[i] = f2tf32(af[i]);
            as[i] = f2tf32(af[i] - __uint_as_float(ab[i]));
        }

#pragma unroll
        for (int nt = 0; nt < 16; nt++) {
            // B fragment: B(k,n) = W[n][k];  n = nt*8+g, k = ks*8+tg (+4)
            const float* wp = w_s + (nt * 8 + g) * 132 + ks * 8 + tg;
            float bf0 = wp[0];
            float bf1 = wp[4];
            uint32_t bb0 = f2tf32(bf0);
            uint32_t bb1 = f2tf32(bf1);
            uint32_t bs0 = f2tf32(bf0 - __uint_as_float(bb0));
            uint32_t bs1 = f2tf32(bf1 - __uint_as_float(bb1));

            mma_tf32(acc[nt], ab, bb0, bb1);  // big*big
            mma_tf32(acc[nt], ab, bs0, bs1);  // big*small
            mma_tf32(acc[nt], as, bb0, bb1);  // small*big
        }
    }

    // Epilogue: c0/c1 -> (row g, cols 2tg, 2tg+1); c2/c3 -> row g+8.
#pragma unroll
    for (int nt = 0; nt < 16; nt++) {
        if (ok0) {
            float* op = out + rA0 * DIM + nt * 8 + tg * 2;
            op[0] = acc[nt][0];
            op[1] = acc[nt][1];
        }
        if (ok1) {
            float* op = out + rA1 * DIM + nt * 8 + tg * 2;
            op[0] = acc[nt][2];
            op[1] = acc[nt][3];
        }
    }
}

// ---------------------------------------------------------------------------
// Launch. Inputs: x, W, vals, src, dst. Output float32 [N_NODES, DIM].
// out = segment_sum(vals * x[src], dst) @ W^T
// ---------------------------------------------------------------------------
extern "C" void kernel_launch(void* const* d_in, const int* in_sizes, int n_in,
                              void* d_out, int out_size) {
    const float* x    = (const float*)d_in[0];
    const float* W    = (const float*)d_in[1];
    const float* vals = (const float*)d_in[2];
    const int*   src  = (const int*)d_in[3];
    const int*   dst  = (const int*)d_in[4];
    float*       out  = (float*)d_out;

    const int smem = 128 * 132 * sizeof(float);
    cudaFuncSetAttribute(mma_gemm_kernel, cudaFuncAttributeMaxDynamicSharedMemorySize, smem);

    const int EB = (N_EDGES + 255) / 256;

    zero_cnt_kernel<<<(N_NODES + 255) / 256, 256>>>();
    hist_kernel<<<EB, 256>>>(dst);
    scan_a_kernel<<<NB_SCAN, 256>>>();
    scan_b_kernel<<<NB_SCAN, 256>>>();
    scatter_kernel<<<EB, 256>>>(vals, src, dst);
    reduce_kernel<<<(N_NODES + 7) / 8, 256>>>(x);
    mma_gemm_kernel<<<(N_NODES + 127) / 128, 256, smem>>>(W, out);
}